// round 10
// baseline (speedup 1.0000x reference)
#include <cuda_runtime.h>
#include <cuda_bf16.h>
#include <cuda_fp16.h>

// GINConv forward: out = segment_sum(X[ci]) @ W  ==  segment_sum((X@W)[ci])
// Kernel 1: Y = X @ W, stored fp16 (proven; rel_err 2e-4 << 1e-3)
// Kernel 2: out = segment_sum(Y[ci])  — QUARTER-warp per node: 8 lanes x
//           uint4 = one full 128B fp16 row per gather instruction, so every
//           LDG serves 4 nodes -> per-edge instruction count halved vs R8.

#define D_FEAT 64
#define N_NODES_MAX 100000

// Scratch for Y in fp16 (12.8 MB). __device__ global: allowed (no alloc).
__device__ __align__(16) __half g_Yh[(size_t)N_NODES_MAX * D_FEAT];

// ---- packed f32x2 helpers (sm_103a) ----
__device__ __forceinline__ unsigned long long pk2(float lo, float hi) {
    unsigned long long r;
    asm("mov.b64 %0, {%1, %2};" : "=l"(r) : "f"(lo), "f"(hi));
    return r;
}
__device__ __forceinline__ void unpk2(unsigned long long v, float& lo, float& hi) {
    asm("mov.b64 {%0, %1}, %2;" : "=f"(lo), "=f"(hi) : "l"(v));
}
__device__ __forceinline__ void fma2(unsigned long long& d,
                                     unsigned long long a,
                                     unsigned long long b) {
    asm("fma.rn.f32x2 %0, %1, %2, %0;" : "+l"(d) : "l"(a), "l"(b));
}

// Accumulate 8 fp16 values (one uint4) into two float4 accumulators.
__device__ __forceinline__ void acc8(float4& lo, float4& hi, const uint4 u) {
    const float2 f0 = __half22float2(*reinterpret_cast<const __half2*>(&u.x));
    const float2 f1 = __half22float2(*reinterpret_cast<const __half2*>(&u.y));
    const float2 f2 = __half22float2(*reinterpret_cast<const __half2*>(&u.z));
    const float2 f3 = __half22float2(*reinterpret_cast<const __half2*>(&u.w));
    lo.x += f0.x; lo.y += f0.y; lo.z += f1.x; lo.w += f1.y;
    hi.x += f2.x; hi.y += f2.y; hi.z += f3.x; hi.w += f3.y;
}

// ================= Kernel 1: Y = X @ W (fp16 out) =================
// 64-row tile per block, 256 threads as 16x16, each thread a 4x4 micro-tile.
__global__ __launch_bounds__(256) void gemm_xw_kernel(
    const float* __restrict__ X,
    const float* __restrict__ W,
    uint2* __restrict__ Yh2,      // [n_rows * 16] uint2 (4 halves each)
    int n_rows)
{
    __shared__ __align__(16) float Xs[D_FEAT][68];               // 17.4 KB
    __shared__ __align__(16) unsigned long long Wp[D_FEAT * 32]; // 16 KB

    const int tid = threadIdx.x;
    const int ty = tid >> 4;
    const int tx = tid & 15;
    const int base = blockIdx.x * 64;

    #pragma unroll
    for (int i = tid; i < 1024; i += 256) {
        const float4 w4 = reinterpret_cast<const float4*>(W)[i];
        const int k = i >> 4, p = i & 15;
        Wp[k * 32 + 2 * p + 0] = pk2(w4.x, w4.y);
        Wp[k * 32 + 2 * p + 1] = pk2(w4.z, w4.w);
    }
    #pragma unroll
    for (int i = tid; i < 1024; i += 256) {
        const int r = i >> 4, q = i & 15;
        float4 v = make_float4(0.f, 0.f, 0.f, 0.f);
        if (base + r < n_rows)
            v = reinterpret_cast<const float4*>(X)[(size_t)(base + r) * 16 + q];
        *reinterpret_cast<float4*>(&Xs[r][q * 4]) = v;
    }
    __syncthreads();

    unsigned long long acc[4][2] = {};

    #pragma unroll 4
    for (int k = 0; k < D_FEAT; ++k) {
        const longlong2 w2 =
            reinterpret_cast<const longlong2*>(Wp + k * 32)[tx];
        #pragma unroll
        for (int j = 0; j < 4; ++j) {
            const float x = Xs[ty * 4 + j][k];
            const unsigned long long xx = pk2(x, x);
            fma2(acc[j][0], xx, (unsigned long long)w2.x);
            fma2(acc[j][1], xx, (unsigned long long)w2.y);
        }
    }

    #pragma unroll
    for (int j = 0; j < 4; ++j) {
        const int row = base + ty * 4 + j;
        if (row < n_rows) {
            float a, b, c, d;
            unpk2(acc[j][0], a, b);
            unpk2(acc[j][1], c, d);
            const __half2 h0 = __float22half2_rn(make_float2(a, b));
            const __half2 h1 = __float22half2_rn(make_float2(c, d));
            uint2 u;
            u.x = *reinterpret_cast<const unsigned*>(&h0);
            u.y = *reinterpret_cast<const unsigned*>(&h1);
            Yh2[(size_t)row * 16 + tx] = u;
        }
    }
}

// ============ Kernel 2: out = segment_sum(Y[ci]) ============
// Quarter-warp (8 lanes) per node; lane fl owns uint4 chunk fl (8 halves)
// of the 128B fp16 row. Warp = 4 nodes, so each LDG instruction serves 4
// nodes' edges. 2-deep unroll: 2 independent gathers in flight (1KB/warp).
__global__ __launch_bounds__(128, 12) void gather_sum_kernel(
    const uint4* __restrict__ Yh4,
    const int* __restrict__ rp,
    const int* __restrict__ ci,
    float4* __restrict__ out4,
    int n_nodes)
{
    const int tid  = threadIdx.x;
    const int qw   = tid >> 3;     // quarter-warp id within block: 0..15
    const int fl   = tid & 7;      // uint4 index within the 128B row
    const int node = blockIdx.x * 16 + qw;
    if (node >= n_nodes) return;

    const int start = __ldg(&rp[node]);
    const int end   = __ldg(&rp[node + 1]);

    float4 a0lo = make_float4(0.f, 0.f, 0.f, 0.f);
    float4 a0hi = a0lo, a1lo = a0lo, a1hi = a0lo;

    int e = start;
    for (; e + 2 <= end; e += 2) {
        const int c0 = __ldg(&ci[e + 0]);
        const int c1 = __ldg(&ci[e + 1]);
        const uint4 v0 = __ldg(&Yh4[(size_t)c0 * 8 + fl]);
        const uint4 v1 = __ldg(&Yh4[(size_t)c1 * 8 + fl]);
        acc8(a0lo, a0hi, v0);
        acc8(a1lo, a1hi, v1);
    }
    if (e < end) {
        const int c = __ldg(&ci[e]);
        const uint4 v = __ldg(&Yh4[(size_t)c * 8 + fl]);
        acc8(a0lo, a0hi, v);
    }

    float4 rlo, rhi;
    rlo.x = a0lo.x + a1lo.x; rlo.y = a0lo.y + a1lo.y;
    rlo.z = a0lo.z + a1lo.z; rlo.w = a0lo.w + a1lo.w;
    rhi.x = a0hi.x + a1hi.x; rhi.y = a0hi.y + a1hi.y;
    rhi.z = a0hi.z + a1hi.z; rhi.w = a0hi.w + a1hi.w;

    // Each lane writes 8 consecutive floats: quarter-warp covers the full
    // 256B fp32 row; warp covers 4 consecutive rows (1KB contiguous).
    out4[(size_t)node * 16 + 2 * fl + 0] = rlo;
    out4[(size_t)node * 16 + 2 * fl + 1] = rhi;
}

extern "C" void kernel_launch(void* const* d_in, const int* in_sizes, int n_in,
                              void* d_out, int out_size) {
    const float* X  = (const float*)d_in[0];   // [100000, 64]
    const float* W  = (const float*)d_in[1];   // [64, 64]
    const int*   rp = (const int*)d_in[2];     // [100001]
    const int*   ci = (const int*)d_in[3];     // [1600000]
    float* out = (float*)d_out;                // [100000, 64]

    const int n_nodes = in_sizes[2] - 1;       // 100000

    __half* Yptr = nullptr;
    cudaGetSymbolAddress((void**)&Yptr, g_Yh);

    const int blocks1 = (n_nodes + 63) / 64;
    gemm_xw_kernel<<<blocks1, 256>>>(X, W, reinterpret_cast<uint2*>(Yptr),
                                     n_nodes);

    const int blocks2 = (n_nodes + 15) / 16;
    gather_sum_kernel<<<blocks2, 128>>>(
        reinterpret_cast<const uint4*>(Yptr), rp, ci,
        reinterpret_cast<float4*>(out), n_nodes);
}

// round 11
// speedup vs baseline: 1.2373x; 1.2373x over previous
#include <cuda_runtime.h>
#include <cuda_bf16.h>
#include <cuda_fp16.h>

// GINConv forward: out = segment_sum(X[ci]) @ W  ==  segment_sum((X@W)[ci])
// Kernel 1: Y = X @ W, stored fp16 (proven)
// Kernel 2: out = segment_sum(Y[ci]) — R8's proven half-warp schedule
//           (4 broadcast ci loads + 4 independent uint2 gathers per trip),
//           accumulation now packed fp16 HADD2 (3x fewer value ops/edge);
//           4 parallel accumulator sets keep each fp16 chain ~deg/4 adds.

#define D_FEAT 64
#define N_NODES_MAX 100000

// Scratch for Y in fp16 (12.8 MB). __device__ global: allowed (no alloc).
__device__ __align__(16) __half g_Yh[(size_t)N_NODES_MAX * D_FEAT];

// ---- packed f32x2 helpers (sm_103a) ----
__device__ __forceinline__ unsigned long long pk2(float lo, float hi) {
    unsigned long long r;
    asm("mov.b64 %0, {%1, %2};" : "=l"(r) : "f"(lo), "f"(hi));
    return r;
}
__device__ __forceinline__ void unpk2(unsigned long long v, float& lo, float& hi) {
    asm("mov.b64 {%0, %1}, %2;" : "=f"(lo), "=f"(hi) : "l"(v));
}
__device__ __forceinline__ void fma2(unsigned long long& d,
                                     unsigned long long a,
                                     unsigned long long b) {
    asm("fma.rn.f32x2 %0, %1, %2, %0;" : "+l"(d) : "l"(a), "l"(b));
}

// Packed fp16 accumulate: a += v  (two add.f16x2 per uint2 = 4 halves)
__device__ __forceinline__ void hacc(uint2& a, const uint2 v) {
    __half2& alo = *reinterpret_cast<__half2*>(&a.x);
    __half2& ahi = *reinterpret_cast<__half2*>(&a.y);
    alo = __hadd2(alo, *reinterpret_cast<const __half2*>(&v.x));
    ahi = __hadd2(ahi, *reinterpret_cast<const __half2*>(&v.y));
}

// Convert uint2 (4 halves) to float4
__device__ __forceinline__ float4 h4f(const uint2 u) {
    const float2 f0 = __half22float2(*reinterpret_cast<const __half2*>(&u.x));
    const float2 f1 = __half22float2(*reinterpret_cast<const __half2*>(&u.y));
    return make_float4(f0.x, f0.y, f1.x, f1.y);
}

// ================= Kernel 1: Y = X @ W (fp16 out) =================
// 64-row tile per block, 256 threads as 16x16, each thread a 4x4 micro-tile.
__global__ __launch_bounds__(256) void gemm_xw_kernel(
    const float* __restrict__ X,
    const float* __restrict__ W,
    uint2* __restrict__ Yh2,      // [n_rows * 16] uint2 (4 halves each)
    int n_rows)
{
    __shared__ __align__(16) float Xs[D_FEAT][68];               // 17.4 KB
    __shared__ __align__(16) unsigned long long Wp[D_FEAT * 32]; // 16 KB

    const int tid = threadIdx.x;
    const int ty = tid >> 4;
    const int tx = tid & 15;
    const int base = blockIdx.x * 64;

    #pragma unroll
    for (int i = tid; i < 1024; i += 256) {
        const float4 w4 = reinterpret_cast<const float4*>(W)[i];
        const int k = i >> 4, p = i & 15;
        Wp[k * 32 + 2 * p + 0] = pk2(w4.x, w4.y);
        Wp[k * 32 + 2 * p + 1] = pk2(w4.z, w4.w);
    }
    #pragma unroll
    for (int i = tid; i < 1024; i += 256) {
        const int r = i >> 4, q = i & 15;
        float4 v = make_float4(0.f, 0.f, 0.f, 0.f);
        if (base + r < n_rows)
            v = reinterpret_cast<const float4*>(X)[(size_t)(base + r) * 16 + q];
        *reinterpret_cast<float4*>(&Xs[r][q * 4]) = v;
    }
    __syncthreads();

    unsigned long long acc[4][2] = {};

    #pragma unroll 4
    for (int k = 0; k < D_FEAT; ++k) {
        const longlong2 w2 =
            reinterpret_cast<const longlong2*>(Wp + k * 32)[tx];
        #pragma unroll
        for (int j = 0; j < 4; ++j) {
            const float x = Xs[ty * 4 + j][k];
            const unsigned long long xx = pk2(x, x);
            fma2(acc[j][0], xx, (unsigned long long)w2.x);
            fma2(acc[j][1], xx, (unsigned long long)w2.y);
        }
    }

    #pragma unroll
    for (int j = 0; j < 4; ++j) {
        const int row = base + ty * 4 + j;
        if (row < n_rows) {
            float a, b, c, d;
            unpk2(acc[j][0], a, b);
            unpk2(acc[j][1], c, d);
            const __half2 h0 = __float22half2_rn(make_float2(a, b));
            const __half2 h1 = __float22half2_rn(make_float2(c, d));
            uint2 u;
            u.x = *reinterpret_cast<const unsigned*>(&h0);
            u.y = *reinterpret_cast<const unsigned*>(&h1);
            Yh2[(size_t)row * 16 + tx] = u;
        }
    }
}

// ============ Kernel 2: out = segment_sum(Y[ci]) ============
// Half-warp (16 lanes) per node; lane fl owns 4 halves (uint2) of the row.
// 4 broadcast ci loads + 4 independent gathers per trip (proven R8 schedule);
// packed HADD2 accumulation into 4 independent fp16 accumulator sets.
__global__ __launch_bounds__(128, 12) void gather_sum_kernel(
    const uint2* __restrict__ Yh2,
    const int* __restrict__ rp,
    const int* __restrict__ ci,
    float4* __restrict__ out4,
    int n_nodes)
{
    const int tid  = threadIdx.x;
    const int half = tid >> 4;     // half-warp id within block: 0..7
    const int fl   = tid & 15;     // uint2 index within the 128B row
    const int node = blockIdx.x * 8 + half;
    if (node >= n_nodes) return;

    const int start = __ldg(&rp[node]);
    const int end   = __ldg(&rp[node + 1]);

    uint2 a0 = make_uint2(0u, 0u);   // half2 zeros
    uint2 a1 = a0, a2 = a0, a3 = a0;

    int e = start;
    for (; e + 4 <= end; e += 4) {
        const int c0 = __ldg(&ci[e + 0]);
        const int c1 = __ldg(&ci[e + 1]);
        const int c2 = __ldg(&ci[e + 2]);
        const int c3 = __ldg(&ci[e + 3]);
        const uint2 v0 = __ldg(&Yh2[(size_t)c0 * 16 + fl]);
        const uint2 v1 = __ldg(&Yh2[(size_t)c1 * 16 + fl]);
        const uint2 v2 = __ldg(&Yh2[(size_t)c2 * 16 + fl]);
        const uint2 v3 = __ldg(&Yh2[(size_t)c3 * 16 + fl]);
        hacc(a0, v0);
        hacc(a1, v1);
        hacc(a2, v2);
        hacc(a3, v3);
    }
    for (; e < end; ++e) {
        const int c = __ldg(&ci[e]);
        const uint2 v = __ldg(&Yh2[(size_t)c * 16 + fl]);
        hacc(a0, v);
    }

    // Final combine in fp32 (one conversion per accumulator set)
    const float4 f0 = h4f(a0);
    const float4 f1 = h4f(a1);
    const float4 f2 = h4f(a2);
    const float4 f3 = h4f(a3);

    float4 r;
    r.x = (f0.x + f1.x) + (f2.x + f3.x);
    r.y = (f0.y + f1.y) + (f2.y + f3.y);
    r.z = (f0.z + f1.z) + (f2.z + f3.z);
    r.w = (f0.w + f1.w) + (f2.w + f3.w);

    out4[(size_t)node * 16 + fl] = r;   // warp = 2 consecutive rows: coalesced
}

extern "C" void kernel_launch(void* const* d_in, const int* in_sizes, int n_in,
                              void* d_out, int out_size) {
    const float* X  = (const float*)d_in[0];   // [100000, 64]
    const float* W  = (const float*)d_in[1];   // [64, 64]
    const int*   rp = (const int*)d_in[2];     // [100001]
    const int*   ci = (const int*)d_in[3];     // [1600000]
    float* out = (float*)d_out;                // [100000, 64]

    const int n_nodes = in_sizes[2] - 1;       // 100000

    __half* Yptr = nullptr;
    cudaGetSymbolAddress((void**)&Yptr, g_Yh);
    uint2* Yh2 = reinterpret_cast<uint2*>(Yptr);

    const int blocks1 = (n_nodes + 63) / 64;
    gemm_xw_kernel<<<blocks1, 256>>>(X, W, Yh2, n_nodes);

    const int blocks2 = (n_nodes + 7) / 8;
    gather_sum_kernel<<<blocks2, 128>>>(
        Yh2, rp, ci, reinterpret_cast<float4*>(out), n_nodes);
}